// round 15
// baseline (speedup 1.0000x reference)
#include <cuda_runtime.h>
#include <cuda_fp16.h>
#include <cstdint>

#define NN    4096
#define FIN   128
#define NH    8
#define FO    64
#define FTOT  512
#define KT    64
#define NSPL  4
#define JSPL  (NN / NSPL)          // 1024 p per split
#define NKT   (JSPL / KT)          // 16 tiles per split
#define LOG2E 1.4426950408889634f

#define VROWS   72
#define VSTR    72                 // f16 per SMEM row (64 k + 8 pad)
#define STG_V   (VROWS * VSTR * 2) // 10368 B per stage
#define STG_T   256                // 64 floats (tgt*L) per stage
#define SMEM_DYN (3 * STG_V + 3 * STG_T)

// ---------------- scratch (static device memory only) ----------------
// j-axis stored PERMUTED: p = (n%8)*512 + n/8 (reduction over j is order-
// invariant; vh/tpf/adjb agree on p).
__device__ float g_src[NH * NN];
__device__ unsigned g_Tbits[NH];               // atomicMax idempotent across replays
__device__ unsigned g_adjb[NN * NN / 32];      // bits in p-order per row
__device__ __half g_vh[NH * FO * NN];          // V^T f16: [h][o][p]
__device__ float g_tpf[NH * NN];               // tgt*LOG2E at p
__device__ float g_part[NSPL][NH * NN * FO];   // split numerators (32 MB)
__device__ float g_psum[NSPL][NH * NN];        // split denominators
__device__ unsigned g_flag[NH * (NN / 128)];   // combine tickets (reset by gemmpack)

// ---------------- helpers ----------------
__device__ __forceinline__ unsigned encf(float f) {
    unsigned b = __float_as_uint(f);
    return (b & 0x80000000u) ? ~b : (b | 0x80000000u);
}
__device__ __forceinline__ float decf(unsigned k) {
    unsigned b = (k & 0x80000000u) ? (k & 0x7FFFFFFFu) : ~k;
    return __uint_as_float(b);
}
__device__ __forceinline__ unsigned long long pack2(float x, float y) {
    unsigned long long r;
    asm("mov.b64 %0, {%1, %2};" : "=l"(r) : "f"(x), "f"(y));
    return r;
}
__device__ __forceinline__ void unpack2(unsigned long long v, float& x, float& y) {
    asm("mov.b64 {%0, %1}, %2;" : "=f"(x), "=f"(y) : "l"(v));
}
__device__ __forceinline__ unsigned long long add2(unsigned long long a,
                                                   unsigned long long b) {
    unsigned long long d;
    asm("add.rn.f32x2 %0, %1, %2;" : "=l"(d) : "l"(a), "l"(b));
    return d;
}
__device__ __forceinline__ unsigned long long ffma2(unsigned long long a,
                                                    unsigned long long b,
                                                    unsigned long long c) {
    unsigned long long d;
    asm("fma.rn.f32x2 %0, %1, %2, %3;" : "=l"(d) : "l"(a), "l"(b), "l"(c));
    return d;
}
__device__ __forceinline__ uint32_t f16x2(float lo, float hi) {
    uint32_t r;
    asm("cvt.rn.f16x2.f32 %0, %1, %2;" : "=r"(r) : "f"(hi), "f"(lo));
    return r;
}
__device__ __forceinline__ uint32_t ex2_h2(uint32_t arg) {
    uint32_t r;
    asm("ex2.approx.f16x2 %0, %1;" : "=r"(r) : "r"(arg));
    return r;
}
__device__ __forceinline__ uint32_t smem_u32(const void* p) {
    uint32_t a;
    asm("{ .reg .u64 t; cvta.to.shared.u64 t, %1; cvt.u32.u64 %0, t; }"
        : "=r"(a) : "l"(p));
    return a;
}
__device__ __forceinline__ void cp16(uint32_t dst, const void* src) {
    asm volatile("cp.async.cg.shared.global [%0], [%1], 16;"
                 :: "r"(dst), "l"(src) : "memory");
}
__device__ __forceinline__ void cp_commit() {
    asm volatile("cp.async.commit_group;" ::: "memory");
}
__device__ __forceinline__ void mma_f16(float c[4], uint32_t a0, uint32_t a1,
                                        uint32_t a2, uint32_t a3,
                                        uint32_t b0, uint32_t b1) {
    asm volatile(
        "mma.sync.aligned.m16n8k16.row.col.f32.f16.f16.f32 "
        "{%0,%1,%2,%3}, {%4,%5,%6,%7}, {%8,%9}, {%0,%1,%2,%3};"
        : "+f"(c[0]), "+f"(c[1]), "+f"(c[2]), "+f"(c[3])
        : "r"(a0), "r"(a1), "r"(a2), "r"(a3), "r"(b0), "r"(b1));
}

// ---------------- kernel A: hW GEMM + fused preprocessing (permuted j) ----------------
__global__ void __launch_bounds__(256, 2)
k_gemmpack(const float* __restrict__ H, const float* __restrict__ W,
           const float* __restrict__ aprm, const int* __restrict__ adj) {
    __shared__ float sA[128][36];
    __shared__ float sW[32][64];
    const int rb = blockIdx.x, cb = blockIdx.y, t = threadIdx.x;
    const int row0 = rb * 128, col0 = cb * 64;
    const int h = rb >> 2, rb4 = rb & 3;
    const int r = t >> 3, c0 = (t & 7) * 8;

    if (rb == 0 && cb == 0 && t < NH * (NN / 128)) g_flag[t] = 0u;

    unsigned long long accP[4][4];
#pragma unroll
    for (int i = 0; i < 4; ++i)
#pragma unroll
        for (int p = 0; p < 4; ++p) accP[i][p] = 0ull;

    for (int kk = 0; kk < FIN; kk += 32) {
#pragma unroll
        for (int u = 0; u < 4; ++u) {
            int idx = t + u * 256;
            int rr = idx >> 3, q = idx & 7;
            float4 v = *(const float4*)(H + (size_t)(row0 + rr) * FIN + kk + q * 4);
            *(float4*)&sA[rr][q * 4] = v;
        }
#pragma unroll
        for (int u = 0; u < 2; ++u) {
            int idx = t + u * 256;
            int k = idx >> 4, q = idx & 15;
            float4 v = *(const float4*)(W + (size_t)(kk + k) * FTOT + col0 + q * 4);
            *(float4*)&sW[k][q * 4] = v;
        }
        __syncthreads();
#pragma unroll
        for (int k = 0; k < 32; ++k) {
            float4 w0 = *(const float4*)&sW[k][c0];
            float4 w1 = *(const float4*)&sW[k][c0 + 4];
            unsigned long long wp0 = pack2(w0.x, w0.y);
            unsigned long long wp1 = pack2(w0.z, w0.w);
            unsigned long long wp2 = pack2(w1.x, w1.y);
            unsigned long long wp3 = pack2(w1.z, w1.w);
#pragma unroll
            for (int i = 0; i < 4; ++i) {
                float av = sA[r + 32 * i][k];
                unsigned long long aP = pack2(av, av);
                accP[i][0] = ffma2(aP, wp0, accP[i][0]);
                accP[i][1] = ffma2(aP, wp1, accP[i][1]);
                accP[i][2] = ffma2(aP, wp2, accP[i][2]);
                accP[i][3] = ffma2(aP, wp3, accP[i][3]);
            }
        }
        __syncthreads();
    }

    float v[4][8];
#pragma unroll
    for (int i = 0; i < 4; ++i)
#pragma unroll
        for (int p = 0; p < 4; ++p)
            unpack2(accP[i][p], v[i][2 * p], v[i][2 * p + 1]);

    // ---- src/tgt dots; src at true n, tgt*L table at permuted p ----
    {
        const float* ap = aprm + h * 128 + c0;
        float s[4] = {0.f, 0.f, 0.f, 0.f}, tg[4] = {0.f, 0.f, 0.f, 0.f};
#pragma unroll
        for (int k = 0; k < 8; ++k) {
            float av = ap[k], bv = ap[64 + k];
#pragma unroll
            for (int i = 0; i < 4; ++i) {
                s[i]  = fmaf(v[i][k], av, s[i]);
                tg[i] = fmaf(v[i][k], bv, tg[i]);
            }
        }
#pragma unroll
        for (int off = 4; off; off >>= 1)
#pragma unroll
            for (int i = 0; i < 4; ++i) {
                s[i]  += __shfl_down_sync(0xFFFFFFFFu, s[i], off, 8);
                tg[i] += __shfl_down_sync(0xFFFFFFFFu, tg[i], off, 8);
            }
        if ((t & 7) == 0) {
            unsigned emax = 0u;
#pragma unroll
            for (int i = 0; i < 4; ++i) {
                const int np = rb4 * 128 + r + 32 * i;          // p-local
                const int n = np * 8 + cb;                      // true node
                g_src[h * NN + n] = s[i];
                unsigned e = encf(tg[i]);
                emax = e > emax ? e : emax;
                g_tpf[h * NN + cb * 512 + np] = tg[i] * LOG2E;
            }
            atomicMax(&g_Tbits[h], emax);
        }
    }

    // ---- V^T f16 write, permuted: contiguous per block ----
    {
        __half* vbase = g_vh + (size_t)h * FO * NN + (size_t)cb * 512 + rb4 * 128 + r;
#pragma unroll
        for (int k = 0; k < 8; ++k)
#pragma unroll
            for (int i = 0; i < 4; ++i)
                vbase[(size_t)(c0 + k) * NN + 32 * i] = __float2half(v[i][k]);
    }

    // ---- adjacency pack, permuted via ballot ----
    {
        const int lane = t & 31;
        const int warp_g = (cb * gridDim.x + rb) * 8 + (t >> 5);   // 0..2047
#pragma unroll 2
        for (int task = warp_g; task < NN * 16; task += 2048) {
            const int i = task >> 4, jb = task & 15;
            const int4* p4 = (const int4*)(adj + (size_t)i * NN + jb * 256 + lane * 8);
            int4 a = p4[0], b = p4[1];
            unsigned byt =
                (unsigned)(a.x != 0)        | ((unsigned)(a.y != 0) << 1) |
                ((unsigned)(a.z != 0) << 2) | ((unsigned)(a.w != 0) << 3) |
                ((unsigned)(b.x != 0) << 4) | ((unsigned)(b.y != 0) << 5) |
                ((unsigned)(b.z != 0) << 6) | ((unsigned)(b.w != 0) << 7);
            unsigned wsel = 0;
#pragma unroll
            for (int c = 0; c < 8; ++c) {
                unsigned bal = __ballot_sync(0xFFFFFFFFu, (byt >> c) & 1u);
                if (lane == c) wsel = bal;
            }
            if (lane < 8)
                g_adjb[(size_t)i * (NN / 32) + lane * 16 + jb] = wsel;
        }
    }
}

// ---------------- kernel C: fused masked-softmax @ V + fused combine ----------------
__global__ void __launch_bounds__(128, 8)
k_attn_mma(const unsigned* __restrict__ adjb, float* __restrict__ part,
           float* __restrict__ psums, float* __restrict__ outp) {
    extern __shared__ float dynf[];
    __half* svh = (__half*)dynf;
    __shared__ unsigned s_old;

    const int head  = blockIdx.x;
    const int ibase = blockIdx.y * 128;
    const int spl   = blockIdx.z;
    const int jbase = spl * JSPL;
    const int t     = threadIdx.x;
    const int wid   = t >> 5;
    const int lane  = t & 31;
    const int g     = lane >> 2;
    const int tg4   = lane & 3;

    const int rbase = ibase + wid * 32 + g;

    const float Th = decf(g_Tbits[head]);
    unsigned long long srcP[4];
    float c8[4];                            // -0.8 * mm  (0.2*eL - mm = 0.2*x + c8)
#pragma unroll
    for (int rg = 0; rg < 4; ++rg) {
        float src = g_src[head * NN + rbase + rg * 8];
        float e0 = src + Th;
        float mm = fmaxf(e0, 0.2f * e0) * LOG2E;
        float sL = src * LOG2E - mm;
        srcP[rg] = pack2(sL, sL);
        c8[rg] = -0.8f * mm;
    }

    const unsigned* abase = adjb + (size_t)rbase * (NN / 32) + (jbase / 32);
    const __half* vhp = g_vh + (size_t)head * FO * NN + jbase;
    const float* tpp = g_tpf + (size_t)head * NN + jbase;

    const uint32_t svb = smem_u32(dynf);
    const uint32_t stb = svb + 3 * STG_V;
    const float2* stp = (const float2*)((const char*)dynf + 3 * STG_V);

    for (int idx = t; idx < 3 * 8 * VSTR; idx += 128) {
        int st = idx / (8 * VSTR), rem = idx % (8 * VSTR);
        int rr = rem / VSTR, kk = rem % VSTR;
        svh[st * (STG_V / 2) + (64 + rr) * VSTR + kk] =
            (rr == 0) ? __float2half(1.0f) : __float2half(0.0f);
    }

    float acc[2][9][4];
#pragma unroll
    for (int gr = 0; gr < 2; ++gr)
#pragma unroll
        for (int nb = 0; nb < 9; ++nb)
#pragma unroll
            for (int q = 0; q < 4; ++q) acc[gr][nb][q] = 0.f;

    auto load_tile = [&](int kt, int st) {
        const __half* base = vhp + (size_t)kt * KT;
        const uint32_t sb = svb + (uint32_t)st * STG_V;
#pragma unroll
        for (int u = 0; u < 4; ++u) {
            int idx = t + u * 128;
            int r = idx >> 3, q = idx & 7;
            cp16(sb + (uint32_t)r * (VSTR * 2) + (uint32_t)q * 16,
                 base + (size_t)r * NN + q * 8);
        }
        if (t < 16)
            cp16(stb + (uint32_t)st * STG_T + (uint32_t)t * 16, tpp + kt * 64 + t * 4);
        cp_commit();
    };
    auto load_adj = [&](int kt, unsigned long long wb[4]) {
#pragma unroll
        for (int rg = 0; rg < 4; ++rg) {
            uint2 w2 = *(const uint2*)(abase + (size_t)rg * 8 * (NN / 32) + 2 * kt);
            wb[rg] = (unsigned long long)w2.x | ((unsigned long long)w2.y << 32);
        }
    };

    load_tile(0, 0);
    load_tile(1, 1);
    unsigned long long wbcur[4], wbnext[4];
    load_adj(0, wbcur);

    for (int kt = 0; kt < NKT; ++kt) {
        const int st = kt % 3;
        if (kt + 2 < NKT) {
            asm volatile("cp.async.wait_group 1;" ::: "memory");
        } else {
            asm volatile("cp.async.wait_group 0;" ::: "memory");
        }
        __syncthreads();
        if (kt + 2 < NKT) load_tile(kt + 2, (kt + 2) % 3);
        if (kt + 1 < NKT) load_adj(kt + 1, wbnext);

        const __half* sVs = svh + st * (STG_V / 2);
        const float2* stq = stp + st * (STG_T / 8);

#pragma unroll
        for (int ks = 0; ks < 4; ++ks) {
            const float2 q1 = stq[ks * 8 + tg4];        // tgtL j = ks*16+2tg4, +1
            const float2 q2 = stq[ks * 8 + 4 + tg4];    // tgtL j = +8, +9
            const unsigned long long tAL = pack2(q1.x, q1.y);
            const unsigned long long tBL = pack2(q2.x, q2.y);
            const int shft = ks * 16 + 2 * tg4;

            uint32_t alo[4], ahi[4];
#pragma unroll
            for (int rg = 0; rg < 4; ++rg) {
                const unsigned bs = (unsigned)(wbcur[rg] >> shft);
                const float cc = c8[rg];
                float x1, y1;
                unpack2(add2(srcP[rg], tAL), x1, y1);
                float a1 = fmaxf(x1, fmaf(0.2f, x1, cc));
                float a2 = fmaxf(y1, fmaf(0.2f, y1, cc));
                uint32_t hwA = ex2_h2(f16x2(a1, a2));
                unsigned mA = ((bs & 1u) * 0xFFFFu) | ((bs & 2u) * 0x7FFF8000u);
                alo[rg] = hwA & mA;
                unpack2(add2(srcP[rg], tBL), x1, y1);
                float b1 = fmaxf(x1, fmaf(0.2f, x1, cc));
                float b2 = fmaxf(y1, fmaf(0.2f, y1, cc));
                uint32_t hwB = ex2_h2(f16x2(b1, b2));
                const unsigned bs8 = bs >> 8;
                unsigned mB = ((bs8 & 1u) * 0xFFFFu) | ((bs8 & 2u) * 0x7FFF8000u);
                ahi[rg] = hwB & mB;
            }
            const int kb = ks * 16 + 2 * tg4;
#pragma unroll
            for (int nb = 0; nb < 9; ++nb) {
                const __half* brow = sVs + (nb * 8 + g) * VSTR + kb;
                uint32_t b0 = *(const uint32_t*)(brow);
                uint32_t b1 = *(const uint32_t*)(brow + 8);
                mma_f16(acc[0][nb], alo[0], alo[1], ahi[0], ahi[1], b0, b1);
                mma_f16(acc[1][nb], alo[2], alo[3], ahi[2], ahi[3], b0, b1);
            }
        }
#pragma unroll
        for (int rg = 0; rg < 4; ++rg) wbcur[rg] = wbnext[rg];
    }

    // ---- denominator partials ----
    float* psp = psums + (size_t)spl * (NH * NN) + head * NN;
    if (tg4 == 0) {
        psp[rbase]      = acc[0][8][0];
        psp[rbase + 8]  = acc[0][8][2];
        psp[rbase + 16] = acc[1][8][0];
        psp[rbase + 24] = acc[1][8][2];
    }

    // ---- numerator partials ----
    float* pp = part + (size_t)spl * (NH * NN * FO) + ((size_t)head * NN) * FO;
#pragma unroll
    for (int gr = 0; gr < 2; ++gr) {
        float* o1 = pp + (size_t)(rbase + gr * 16) * FO + 2 * tg4;
        float* o2 = o1 + 8 * FO;
#pragma unroll
        for (int nb = 0; nb < 8; ++nb) {
            *(float2*)(o1 + nb * 8) = make_float2(acc[gr][nb][0], acc[gr][nb][1]);
            *(float2*)(o2 + nb * 8) = make_float2(acc[gr][nb][2], acc[gr][nb][3]);
        }
    }

    // ---- fused combine: last split-block for this (head, i-tile) ----
    __threadfence();
    __syncthreads();
    if (t == 0) s_old = atomicAdd(&g_flag[head * (NN / 128) + blockIdx.y], 1u);
    __syncthreads();
    if (s_old == NSPL - 1) {
        __threadfence();
        const size_t rowoff = ((size_t)head * NN + ibase) * FO;
        float4* op = (float4*)(outp + rowoff);
        const float4* np[NSPL];
        const float* sp[NSPL];
#pragma unroll
        for (int s = 0; s < NSPL; ++s) {
            np[s] = (const float4*)(part + (size_t)s * (NH * NN * FO) + rowoff);
            sp[s] = psums + (size_t)s * (NH * NN) + head * NN + ibase;
        }
        for (int idx = t; idx < 128 * FO / 4; idx += 128) {
            int row = idx >> 4;
            float ssum = sp[0][row] + sp[1][row] + sp[2][row] + sp[3][row];
            float inv = (ssum > 0.f) ? 1.0f / ssum : 0.f;
            float4 a = np[0][idx], b = np[1][idx], c = np[2][idx], d = np[3][idx];
            float4 o;
            o.x = (a.x + b.x + c.x + d.x) * inv;
            o.y = (a.y + b.y + c.y + d.y) * inv;
            o.z = (a.z + b.z + c.z + d.z) * inv;
            o.w = (a.w + b.w + c.w + d.w) * inv;
            op[idx] = o;
        }
    }
}

// ---------------- host launcher ----------------
extern "C" void kernel_launch(void* const* d_in, const int* in_sizes, int n_in,
                              void* d_out, int out_size) {
    const float* H = nullptr; const int* adj = nullptr;
    const float* W = nullptr; const float* a = nullptr;
    for (int i = 0; i < n_in; ++i) {
        switch (in_sizes[i]) {
            case NN * FIN:    H   = (const float*)d_in[i]; break;
            case NN * NN:     adj = (const int*)d_in[i];   break;
            case FIN * FTOT:  W   = (const float*)d_in[i]; break;
            case NH * 2 * FO: a   = (const float*)d_in[i]; break;
        }
    }
    float* out = (float*)d_out;

    unsigned* adjb; cudaGetSymbolAddress((void**)&adjb, g_adjb);
    float* part;    cudaGetSymbolAddress((void**)&part, g_part);
    float* psums;   cudaGetSymbolAddress((void**)&psums, g_psum);

    cudaFuncSetAttribute(k_attn_mma, cudaFuncAttributeMaxDynamicSharedMemorySize,
                         SMEM_DYN);

    k_gemmpack<<<dim3(NN / 128, NH), 256>>>(H, W, a, adj);
    k_attn_mma<<<dim3(NH, NN / 128, NSPL), 128, SMEM_DYN>>>(adjb, part, psums, out);
}

// round 16
// speedup vs baseline: 2.9007x; 2.9007x over previous
#include <cuda_runtime.h>
#include <cuda_fp16.h>
#include <cstdint>

#define NN    4096
#define FIN   128
#define NH    8
#define FO    64
#define FTOT  512
#define KT    64
#define NSPL  2
#define JSPL  (NN / NSPL)          // 2048 p per split
#define NKT   (JSPL / KT)          // 32 tiles per split
#define LOG2E 1.4426950408889634f

#define VROWS   72
#define VSTR    72                 // f16 per SMEM row (64 k + 8 pad)
#define STG_V   (VROWS * VSTR * 2) // 10368 B per stage
#define STG_T   256                // 64 floats (tgt*L) per stage
#define SMEM_DYN (3 * STG_V + 3 * STG_T)

// ---------------- scratch (static device memory only) ----------------
// j-axis stored PERMUTED: p = (n%8)*512 + n/8 (reduction over j is order-
// invariant; vh/tpf/adjb agree on p).
__device__ float g_src[NH * NN];
__device__ unsigned g_Tbits[NH];               // atomicMax idempotent across replays
__device__ unsigned g_adjb[NN * NN / 32];      // bits in p-order per row
__device__ __half g_vh[NH * FO * NN];          // V^T f16: [h][o][p]
__device__ float g_tpf[NH * NN];               // tgt*LOG2E at p
__device__ float g_part[NSPL][NH * NN * FO];   // split numerators
__device__ float g_psum[NSPL][NH * NN];        // split denominators
__device__ unsigned g_flag[NH * (NN / 128)];   // combine tickets (reset by gemmpack)

// ---------------- helpers ----------------
__device__ __forceinline__ unsigned encf(float f) {
    unsigned b = __float_as_uint(f);
    return (b & 0x80000000u) ? ~b : (b | 0x80000000u);
}
__device__ __forceinline__ float decf(unsigned k) {
    unsigned b = (k & 0x80000000u) ? (k & 0x7FFFFFFFu) : ~k;
    return __uint_as_float(b);
}
__device__ __forceinline__ unsigned long long pack2(float x, float y) {
    unsigned long long r;
    asm("mov.b64 %0, {%1, %2};" : "=l"(r) : "f"(x), "f"(y));
    return r;
}
__device__ __forceinline__ void unpack2(unsigned long long v, float& x, float& y) {
    asm("mov.b64 {%0, %1}, %2;" : "=f"(x), "=f"(y) : "l"(v));
}
__device__ __forceinline__ unsigned long long add2(unsigned long long a,
                                                   unsigned long long b) {
    unsigned long long d;
    asm("add.rn.f32x2 %0, %1, %2;" : "=l"(d) : "l"(a), "l"(b));
    return d;
}
__device__ __forceinline__ unsigned long long ffma2(unsigned long long a,
                                                    unsigned long long b,
                                                    unsigned long long c) {
    unsigned long long d;
    asm("fma.rn.f32x2 %0, %1, %2, %3;" : "=l"(d) : "l"(a), "l"(b), "l"(c));
    return d;
}
__device__ __forceinline__ uint32_t f16x2(float lo, float hi) {
    uint32_t r;
    asm("cvt.rn.f16x2.f32 %0, %1, %2;" : "=r"(r) : "f"(hi), "f"(lo));
    return r;
}
__device__ __forceinline__ uint32_t ex2_h2(uint32_t arg) {
    uint32_t r;
    asm("ex2.approx.f16x2 %0, %1;" : "=r"(r) : "r"(arg));
    return r;
}
__device__ __forceinline__ uint32_t smem_u32(const void* p) {
    uint32_t a;
    asm("{ .reg .u64 t; cvta.to.shared.u64 t, %1; cvt.u32.u64 %0, t; }"
        : "=r"(a) : "l"(p));
    return a;
}
__device__ __forceinline__ void cp16(uint32_t dst, const void* src) {
    asm volatile("cp.async.cg.shared.global [%0], [%1], 16;"
                 :: "r"(dst), "l"(src) : "memory");
}
__device__ __forceinline__ void cp_commit() {
    asm volatile("cp.async.commit_group;" ::: "memory");
}
__device__ __forceinline__ void mma_f16(float c[4], uint32_t a0, uint32_t a1,
                                        uint32_t a2, uint32_t a3,
                                        uint32_t b0, uint32_t b1) {
    asm volatile(
        "mma.sync.aligned.m16n8k16.row.col.f32.f16.f16.f32 "
        "{%0,%1,%2,%3}, {%4,%5,%6,%7}, {%8,%9}, {%0,%1,%2,%3};"
        : "+f"(c[0]), "+f"(c[1]), "+f"(c[2]), "+f"(c[3])
        : "r"(a0), "r"(a1), "r"(a2), "r"(a3), "r"(b0), "r"(b1));
}

// ---------------- kernel A: hW GEMM + fused preprocessing (permuted j) ----------------
__global__ void __launch_bounds__(256, 2)
k_gemmpack(const float* __restrict__ H, const float* __restrict__ W,
           const float* __restrict__ aprm, const int* __restrict__ adj) {
    __shared__ float sA[128][36];
    __shared__ float sW[32][64];
    const int rb = blockIdx.x, cb = blockIdx.y, t = threadIdx.x;
    const int row0 = rb * 128, col0 = cb * 64;
    const int h = rb >> 2, rb4 = rb & 3;
    const int r = t >> 3, c0 = (t & 7) * 8;

    if (rb == 0 && cb == 0 && t < NH * (NN / 128)) g_flag[t] = 0u;

    unsigned long long accP[4][4];
#pragma unroll
    for (int i = 0; i < 4; ++i)
#pragma unroll
        for (int p = 0; p < 4; ++p) accP[i][p] = 0ull;

    for (int kk = 0; kk < FIN; kk += 32) {
#pragma unroll
        for (int u = 0; u < 4; ++u) {
            int idx = t + u * 256;
            int rr = idx >> 3, q = idx & 7;
            float4 v = *(const float4*)(H + (size_t)(row0 + rr) * FIN + kk + q * 4);
            *(float4*)&sA[rr][q * 4] = v;
        }
#pragma unroll
        for (int u = 0; u < 2; ++u) {
            int idx = t + u * 256;
            int k = idx >> 4, q = idx & 15;
            float4 v = *(const float4*)(W + (size_t)(kk + k) * FTOT + col0 + q * 4);
            *(float4*)&sW[k][q * 4] = v;
        }
        __syncthreads();
#pragma unroll
        for (int k = 0; k < 32; ++k) {
            float4 w0 = *(const float4*)&sW[k][c0];
            float4 w1 = *(const float4*)&sW[k][c0 + 4];
            unsigned long long wp0 = pack2(w0.x, w0.y);
            unsigned long long wp1 = pack2(w0.z, w0.w);
            unsigned long long wp2 = pack2(w1.x, w1.y);
            unsigned long long wp3 = pack2(w1.z, w1.w);
#pragma unroll
            for (int i = 0; i < 4; ++i) {
                float av = sA[r + 32 * i][k];
                unsigned long long aP = pack2(av, av);
                accP[i][0] = ffma2(aP, wp0, accP[i][0]);
                accP[i][1] = ffma2(aP, wp1, accP[i][1]);
                accP[i][2] = ffma2(aP, wp2, accP[i][2]);
                accP[i][3] = ffma2(aP, wp3, accP[i][3]);
            }
        }
        __syncthreads();
    }

    float v[4][8];
#pragma unroll
    for (int i = 0; i < 4; ++i)
#pragma unroll
        for (int p = 0; p < 4; ++p)
            unpack2(accP[i][p], v[i][2 * p], v[i][2 * p + 1]);

    // ---- src/tgt dots; src at true n, tgt*L table at permuted p ----
    {
        const float* ap = aprm + h * 128 + c0;
        float s[4] = {0.f, 0.f, 0.f, 0.f}, tg[4] = {0.f, 0.f, 0.f, 0.f};
#pragma unroll
        for (int k = 0; k < 8; ++k) {
            float av = ap[k], bv = ap[64 + k];
#pragma unroll
            for (int i = 0; i < 4; ++i) {
                s[i]  = fmaf(v[i][k], av, s[i]);
                tg[i] = fmaf(v[i][k], bv, tg[i]);
            }
        }
#pragma unroll
        for (int off = 4; off; off >>= 1)
#pragma unroll
            for (int i = 0; i < 4; ++i) {
                s[i]  += __shfl_down_sync(0xFFFFFFFFu, s[i], off, 8);
                tg[i] += __shfl_down_sync(0xFFFFFFFFu, tg[i], off, 8);
            }
        if ((t & 7) == 0) {
            unsigned emax = 0u;
#pragma unroll
            for (int i = 0; i < 4; ++i) {
                const int np = rb4 * 128 + r + 32 * i;          // p-local
                const int n = np * 8 + cb;                      // true node
                g_src[h * NN + n] = s[i];
                unsigned e = encf(tg[i]);
                emax = e > emax ? e : emax;
                g_tpf[h * NN + cb * 512 + np] = tg[i] * LOG2E;
            }
            atomicMax(&g_Tbits[h], emax);
        }
    }

    // ---- V^T f16 write, permuted: contiguous per block ----
    {
        __half* vbase = g_vh + (size_t)h * FO * NN + (size_t)cb * 512 + rb4 * 128 + r;
#pragma unroll
        for (int k = 0; k < 8; ++k)
#pragma unroll
            for (int i = 0; i < 4; ++i)
                vbase[(size_t)(c0 + k) * NN + 32 * i] = __float2half(v[i][k]);
    }

    // ---- adjacency pack, permuted via ballot ----
    {
        const int lane = t & 31;
        const int warp_g = (cb * gridDim.x + rb) * 8 + (t >> 5);   // 0..2047
#pragma unroll 2
        for (int task = warp_g; task < NN * 16; task += 2048) {
            const int i = task >> 4, jb = task & 15;
            const int4* p4 = (const int4*)(adj + (size_t)i * NN + jb * 256 + lane * 8);
            int4 a = p4[0], b = p4[1];
            unsigned byt =
                (unsigned)(a.x != 0)        | ((unsigned)(a.y != 0) << 1) |
                ((unsigned)(a.z != 0) << 2) | ((unsigned)(a.w != 0) << 3) |
                ((unsigned)(b.x != 0) << 4) | ((unsigned)(b.y != 0) << 5) |
                ((unsigned)(b.z != 0) << 6) | ((unsigned)(b.w != 0) << 7);
            unsigned wsel = 0;
#pragma unroll
            for (int c = 0; c < 8; ++c) {
                unsigned bal = __ballot_sync(0xFFFFFFFFu, (byt >> c) & 1u);
                if (lane == c) wsel = bal;
            }
            if (lane < 8)
                g_adjb[(size_t)i * (NN / 32) + lane * 16 + jb] = wsel;
        }
    }
}

// ---------------- kernel C: fused masked-softmax @ V + fused combine ----------------
__global__ void __launch_bounds__(128, 4)
k_attn_mma(const unsigned* __restrict__ adjb, float* __restrict__ part,
           float* __restrict__ psums, float* __restrict__ outp) {
    extern __shared__ float dynf[];
    __half* svh = (__half*)dynf;
    __shared__ unsigned s_old;

    const int head  = blockIdx.x;
    const int ibase = blockIdx.y * 128;
    const int spl   = blockIdx.z;
    const int jbase = spl * JSPL;
    const int t     = threadIdx.x;
    const int wid   = t >> 5;
    const int lane  = t & 31;
    const int g     = lane >> 2;
    const int tg4   = lane & 3;

    const int rbase = ibase + wid * 32 + g;

    const float Th = decf(g_Tbits[head]);
    unsigned long long srcP[4];
    float c8[4];                            // -0.8*mm  (0.2*eL - mm = 0.2*x + c8)
#pragma unroll
    for (int rg = 0; rg < 4; ++rg) {
        float src = g_src[head * NN + rbase + rg * 8];
        float e0 = src + Th;
        float mm = fmaxf(e0, 0.2f * e0) * LOG2E;
        float sL = src * LOG2E - mm;
        srcP[rg] = pack2(sL, sL);
        c8[rg] = -0.8f * mm;
    }

    const unsigned* abase = adjb + (size_t)rbase * (NN / 32) + (jbase / 32);
    const __half* vhp = g_vh + (size_t)head * FO * NN + jbase;
    const float* tpp = g_tpf + (size_t)head * NN + jbase;

    const uint32_t svb = smem_u32(dynf);
    const uint32_t stb = svb + 3 * STG_V;
    const float2* stp = (const float2*)((const char*)dynf + 3 * STG_V);

    for (int idx = t; idx < 3 * 8 * VSTR; idx += 128) {
        int st = idx / (8 * VSTR), rem = idx % (8 * VSTR);
        int rr = rem / VSTR, kk = rem % VSTR;
        svh[st * (STG_V / 2) + (64 + rr) * VSTR + kk] =
            (rr == 0) ? __float2half(1.0f) : __float2half(0.0f);
    }

    float acc[2][9][4];
#pragma unroll
    for (int gr = 0; gr < 2; ++gr)
#pragma unroll
        for (int nb = 0; nb < 9; ++nb)
#pragma unroll
            for (int q = 0; q < 4; ++q) acc[gr][nb][q] = 0.f;

    auto load_tile = [&](int kt, int st) {
        const __half* base = vhp + (size_t)kt * KT;
        const uint32_t sb = svb + (uint32_t)st * STG_V;
#pragma unroll
        for (int u = 0; u < 4; ++u) {
            int idx = t + u * 128;
            int r = idx >> 3, q = idx & 7;
            cp16(sb + (uint32_t)r * (VSTR * 2) + (uint32_t)q * 16,
                 base + (size_t)r * NN + q * 8);
        }
        if (t < 16)
            cp16(stb + (uint32_t)st * STG_T + (uint32_t)t * 16, tpp + kt * 64 + t * 4);
        cp_commit();
    };
    auto load_adj = [&](int kt, unsigned long long wb[4]) {
#pragma unroll
        for (int rg = 0; rg < 4; ++rg) {
            uint2 w2 = *(const uint2*)(abase + (size_t)rg * 8 * (NN / 32) + 2 * kt);
            wb[rg] = (unsigned long long)w2.x | ((unsigned long long)w2.y << 32);
        }
    };

    load_tile(0, 0);
    load_tile(1, 1);
    unsigned long long wbcur[4], wbnext[4];
    load_adj(0, wbcur);

    for (int kt = 0; kt < NKT; ++kt) {
        const int st = kt % 3;
        if (kt + 2 < NKT) {
            asm volatile("cp.async.wait_group 1;" ::: "memory");
        } else {
            asm volatile("cp.async.wait_group 0;" ::: "memory");
        }
        __syncthreads();
        if (kt + 2 < NKT) load_tile(kt + 2, (kt + 2) % 3);
        if (kt + 1 < NKT) load_adj(kt + 1, wbnext);

        const __half* sVs = svh + st * (STG_V / 2);
        const float2* stq = stp + st * (STG_T / 8);

#pragma unroll
        for (int ks = 0; ks < 4; ++ks) {
            const float2 q1 = stq[ks * 8 + tg4];        // tgtL j = ks*16+2tg4, +1
            const float2 q2 = stq[ks * 8 + 4 + tg4];    // tgtL j = +8, +9
            const unsigned long long tAL = pack2(q1.x, q1.y);
            const unsigned long long tBL = pack2(q2.x, q2.y);
            const int shft = ks * 16 + 2 * tg4;

            uint32_t alo[4], ahi[4];
#pragma unroll
            for (int rg = 0; rg < 4; ++rg) {
                const unsigned bs = (unsigned)(wbcur[rg] >> shft);
                const float cc = c8[rg];
                float x1, y1;
                unpack2(add2(srcP[rg], tAL), x1, y1);
                float a1 = fmaxf(x1, fmaf(0.2f, x1, cc));
                float a2 = fmaxf(y1, fmaf(0.2f, y1, cc));
                uint32_t hwA = ex2_h2(f16x2(a1, a2));
                unsigned mA = ((bs & 1u) * 0xFFFFu) | ((bs & 2u) * 0x7FFF8000u);
                alo[rg] = hwA & mA;
                unpack2(add2(srcP[rg], tBL), x1, y1);
                float b1 = fmaxf(x1, fmaf(0.2f, x1, cc));
                float b2 = fmaxf(y1, fmaf(0.2f, y1, cc));
                uint32_t hwB = ex2_h2(f16x2(b1, b2));
                const unsigned bs8 = bs >> 8;
                unsigned mB = ((bs8 & 1u) * 0xFFFFu) | ((bs8 & 2u) * 0x7FFF8000u);
                ahi[rg] = hwB & mB;
            }
            const int kb = ks * 16 + 2 * tg4;
#pragma unroll
            for (int nb = 0; nb < 9; ++nb) {
                const __half* brow = sVs + (nb * 8 + g) * VSTR + kb;
                uint32_t b0 = *(const uint32_t*)(brow);
                uint32_t b1 = *(const uint32_t*)(brow + 8);
                mma_f16(acc[0][nb], alo[0], alo[1], ahi[0], ahi[1], b0, b1);
                mma_f16(acc[1][nb], alo[2], alo[3], ahi[2], ahi[3], b0, b1);
            }
        }
#pragma unroll
        for (int rg = 0; rg < 4; ++rg) wbcur[rg] = wbnext[rg];
    }

    // ---- denominator partials ----
    float* psp = psums + (size_t)spl * (NH * NN) + head * NN;
    if (tg4 == 0) {
        psp[rbase]      = acc[0][8][0];
        psp[rbase + 8]  = acc[0][8][2];
        psp[rbase + 16] = acc[1][8][0];
        psp[rbase + 24] = acc[1][8][2];
    }

    // ---- numerator partials ----
    float* pp = part + (size_t)spl * (NH * NN * FO) + ((size_t)head * NN) * FO;
#pragma unroll
    for (int gr = 0; gr < 2; ++gr) {
        float* o1 = pp + (size_t)(rbase + gr * 16) * FO + 2 * tg4;
        float* o2 = o1 + 8 * FO;
#pragma unroll
        for (int nb = 0; nb < 8; ++nb) {
            *(float2*)(o1 + nb * 8) = make_float2(acc[gr][nb][0], acc[gr][nb][1]);
            *(float2*)(o2 + nb * 8) = make_float2(acc[gr][nb][2], acc[gr][nb][3]);
        }
    }

    // ---- fused combine: last split-block for this (head, i-tile) ----
    __threadfence();
    __syncthreads();
    if (t == 0) s_old = atomicAdd(&g_flag[head * (NN / 128) + blockIdx.y], 1u);
    __syncthreads();
    if (s_old == NSPL - 1) {
        __threadfence();
        const size_t rowoff = ((size_t)head * NN + ibase) * FO;
        const float4* n0 = (const float4*)(part + rowoff);
        const float4* n1 = (const float4*)(part + (size_t)NH * NN * FO + rowoff);
        const float* s0 = psums + head * NN + ibase;
        const float* s1 = psums + NH * NN + head * NN + ibase;
        float4* op = (float4*)(outp + rowoff);
        for (int idx = t; idx < 128 * FO / 4; idx += 128) {
            int row = idx >> 4;
            float s = s0[row] + s1[row];
            float inv = (s > 0.f) ? 1.0f / s : 0.f;
            float4 a = n0[idx], b = n1[idx];
            float4 o;
            o.x = (a.x + b.x) * inv;
            o.y = (a.y + b.y) * inv;
            o.z = (a.z + b.z) * inv;
            o.w = (a.w + b.w) * inv;
            op[idx] = o;
        }
    }
}

// ---------------- host launcher ----------------
extern "C" void kernel_launch(void* const* d_in, const int* in_sizes, int n_in,
                              void* d_out, int out_size) {
    const float* H = nullptr; const int* adj = nullptr;
    const float* W = nullptr; const float* a = nullptr;
    for (int i = 0; i < n_in; ++i) {
        switch (in_sizes[i]) {
            case NN * FIN:    H   = (const float*)d_in[i]; break;
            case NN * NN:     adj = (const int*)d_in[i];   break;
            case FIN * FTOT:  W   = (const float*)d_in[i]; break;
            case NH * 2 * FO: a   = (const float*)d_in[i]; break;
        }
    }
    float* out = (float*)d_out;

    unsigned* adjb; cudaGetSymbolAddress((void**)&adjb, g_adjb);
    float* part;    cudaGetSymbolAddress((void**)&part, g_part);
    float* psums;   cudaGetSymbolAddress((void**)&psums, g_psum);

    cudaFuncSetAttribute(k_attn_mma, cudaFuncAttributeMaxDynamicSharedMemorySize,
                         SMEM_DYN);

    k_gemmpack<<<dim3(NN / 128, NH), 256>>>(H, W, a, adj);
    k_attn_mma<<<dim3(NH, NN / 128, NSPL), 128, SMEM_DYN>>>(adjb, part, psums, out);
}

// round 17
// speedup vs baseline: 2.9851x; 1.0291x over previous
#include <cuda_runtime.h>
#include <cuda_fp16.h>
#include <cstdint>

#define NN    4096
#define FIN   128
#define NH    8
#define FO    64
#define FTOT  512
#define KT    64
#define NSPL  2
#define JSPL  (NN / NSPL)          // 2048 p per split
#define NKT   (JSPL / KT)          // 32 tiles per split
#define LOG2E 1.4426950408889634f

#define VROWS   72
#define VSTR    72                 // f16 per SMEM row (64 k + 8 pad)
#define STG_V   (VROWS * VSTR * 2) // 10368 B per stage
#define STG_T   256                // 64 x u32 {B16,D16} per stage
#define SMEM_DYN (3 * STG_V + 3 * STG_T)

// ---------------- scratch (static device memory only) ----------------
// j-axis stored PERMUTED: p = (n%8)*512 + n/8 (reduction over j is order-
// invariant; vh/bd/adjb agree on p).
__device__ float g_src[NH * NN];
__device__ unsigned g_Tbits[NH];               // atomicMax idempotent across replays
__device__ unsigned g_adjb[NN * NN / 32];      // bits in p-order per row
__device__ __half g_vh[NH * FO * NN];          // V^T f16: [h][o][p]
__device__ unsigned g_bd[NH * NN];             // {B=exp2(tL) lo, D=exp2(.2tL) hi} f16x2 at p
__device__ float g_part[NSPL][NH * NN * FO];   // split numerators
__device__ float g_psum[NSPL][NH * NN];        // split denominators
__device__ unsigned g_flag[NH * (NN / 128)];   // combine tickets (reset by gemmpack)

// ---------------- helpers ----------------
__device__ __forceinline__ unsigned encf(float f) {
    unsigned b = __float_as_uint(f);
    return (b & 0x80000000u) ? ~b : (b | 0x80000000u);
}
__device__ __forceinline__ float decf(unsigned k) {
    unsigned b = (k & 0x80000000u) ? (k & 0x7FFFFFFFu) : ~k;
    return __uint_as_float(b);
}
__device__ __forceinline__ float ex2f(float x) {
    float r;
    asm("ex2.approx.f32 %0, %1;" : "=f"(r) : "f"(x));
    return r;
}
__device__ __forceinline__ unsigned long long pack2(float x, float y) {
    unsigned long long r;
    asm("mov.b64 %0, {%1, %2};" : "=l"(r) : "f"(x), "f"(y));
    return r;
}
__device__ __forceinline__ void unpack2(unsigned long long v, float& x, float& y) {
    asm("mov.b64 {%0, %1}, %2;" : "=f"(x), "=f"(y) : "l"(v));
}
__device__ __forceinline__ unsigned long long ffma2(unsigned long long a,
                                                    unsigned long long b,
                                                    unsigned long long c) {
    unsigned long long d;
    asm("fma.rn.f32x2 %0, %1, %2, %3;" : "=l"(d) : "l"(a), "l"(b), "l"(c));
    return d;
}
__device__ __forceinline__ uint32_t f16x2(float lo, float hi) {
    uint32_t r;
    asm("cvt.rn.f16x2.f32 %0, %1, %2;" : "=r"(r) : "f"(hi), "f"(lo));
    return r;
}
__device__ __forceinline__ uint32_t hmul2(uint32_t a, uint32_t b) {
    uint32_t r;
    asm("mul.rn.f16x2 %0, %1, %2;" : "=r"(r) : "r"(a), "r"(b));
    return r;
}
__device__ __forceinline__ uint32_t hmax2(uint32_t a, uint32_t b) {
    uint32_t r;
    asm("max.f16x2 %0, %1, %2;" : "=r"(r) : "r"(a), "r"(b));
    return r;
}
__device__ __forceinline__ uint32_t prmt(uint32_t a, uint32_t b, uint32_t sel) {
    uint32_t r;
    asm("prmt.b32 %0, %1, %2, %3;" : "=r"(r) : "r"(a), "r"(b), "r"(sel));
    return r;
}
__device__ __forceinline__ uint32_t smem_u32(const void* p) {
    uint32_t a;
    asm("{ .reg .u64 t; cvta.to.shared.u64 t, %1; cvt.u32.u64 %0, t; }"
        : "=r"(a) : "l"(p));
    return a;
}
__device__ __forceinline__ void cp16(uint32_t dst, const void* src) {
    asm volatile("cp.async.cg.shared.global [%0], [%1], 16;"
                 :: "r"(dst), "l"(src) : "memory");
}
__device__ __forceinline__ void cp_commit() {
    asm volatile("cp.async.commit_group;" ::: "memory");
}
__device__ __forceinline__ void mma_f16(float c[4], uint32_t a0, uint32_t a1,
                                        uint32_t a2, uint32_t a3,
                                        uint32_t b0, uint32_t b1) {
    asm volatile(
        "mma.sync.aligned.m16n8k16.row.col.f32.f16.f16.f32 "
        "{%0,%1,%2,%3}, {%4,%5,%6,%7}, {%8,%9}, {%0,%1,%2,%3};"
        : "+f"(c[0]), "+f"(c[1]), "+f"(c[2]), "+f"(c[3])
        : "r"(a0), "r"(a1), "r"(a2), "r"(a3), "r"(b0), "r"(b1));
}

// ---------------- kernel A: hW GEMM + fused preprocessing (permuted j) ----------------
__global__ void __launch_bounds__(256, 2)
k_gemmpack(const float* __restrict__ H, const float* __restrict__ W,
           const float* __restrict__ aprm, const int* __restrict__ adj) {
    __shared__ float sA[128][36];
    __shared__ float sW[32][64];
    const int rb = blockIdx.x, cb = blockIdx.y, t = threadIdx.x;
    const int row0 = rb * 128, col0 = cb * 64;
    const int h = rb >> 2, rb4 = rb & 3;
    const int r = t >> 3, c0 = (t & 7) * 8;

    if (rb == 0 && cb == 0 && t < NH * (NN / 128)) g_flag[t] = 0u;

    unsigned long long accP[4][4];
#pragma unroll
    for (int i = 0; i < 4; ++i)
#pragma unroll
        for (int p = 0; p < 4; ++p) accP[i][p] = 0ull;

    for (int kk = 0; kk < FIN; kk += 32) {
#pragma unroll
        for (int u = 0; u < 4; ++u) {
            int idx = t + u * 256;
            int rr = idx >> 3, q = idx & 7;
            float4 v = *(const float4*)(H + (size_t)(row0 + rr) * FIN + kk + q * 4);
            *(float4*)&sA[rr][q * 4] = v;
        }
#pragma unroll
        for (int u = 0; u < 2; ++u) {
            int idx = t + u * 256;
            int k = idx >> 4, q = idx & 15;
            float4 v = *(const float4*)(W + (size_t)(kk + k) * FTOT + col0 + q * 4);
            *(float4*)&sW[k][q * 4] = v;
        }
        __syncthreads();
#pragma unroll
        for (int k = 0; k < 32; ++k) {
            float4 w0 = *(const float4*)&sW[k][c0];
            float4 w1 = *(const float4*)&sW[k][c0 + 4];
            unsigned long long wp0 = pack2(w0.x, w0.y);
            unsigned long long wp1 = pack2(w0.z, w0.w);
            unsigned long long wp2 = pack2(w1.x, w1.y);
            unsigned long long wp3 = pack2(w1.z, w1.w);
#pragma unroll
            for (int i = 0; i < 4; ++i) {
                float av = sA[r + 32 * i][k];
                unsigned long long aP = pack2(av, av);
                accP[i][0] = ffma2(aP, wp0, accP[i][0]);
                accP[i][1] = ffma2(aP, wp1, accP[i][1]);
                accP[i][2] = ffma2(aP, wp2, accP[i][2]);
                accP[i][3] = ffma2(aP, wp3, accP[i][3]);
            }
        }
        __syncthreads();
    }

    float v[4][8];
#pragma unroll
    for (int i = 0; i < 4; ++i)
#pragma unroll
        for (int p = 0; p < 4; ++p)
            unpack2(accP[i][p], v[i][2 * p], v[i][2 * p + 1]);

    // ---- src/tgt dots; src at true n, {B,D} factor table at permuted p ----
    {
        const float* ap = aprm + h * 128 + c0;
        float s[4] = {0.f, 0.f, 0.f, 0.f}, tg[4] = {0.f, 0.f, 0.f, 0.f};
#pragma unroll
        for (int k = 0; k < 8; ++k) {
            float av = ap[k], bv = ap[64 + k];
#pragma unroll
            for (int i = 0; i < 4; ++i) {
                s[i]  = fmaf(v[i][k], av, s[i]);
                tg[i] = fmaf(v[i][k], bv, tg[i]);
            }
        }
#pragma unroll
        for (int off = 4; off; off >>= 1)
#pragma unroll
            for (int i = 0; i < 4; ++i) {
                s[i]  += __shfl_down_sync(0xFFFFFFFFu, s[i], off, 8);
                tg[i] += __shfl_down_sync(0xFFFFFFFFu, tg[i], off, 8);
            }
        if ((t & 7) == 0) {
            unsigned emax = 0u;
#pragma unroll
            for (int i = 0; i < 4; ++i) {
                const int np = rb4 * 128 + r + 32 * i;          // p-local
                const int n = np * 8 + cb;                      // true node
                g_src[h * NN + n] = s[i];
                unsigned e = encf(tg[i]);
                emax = e > emax ? e : emax;
                float tL = tg[i] * LOG2E;
                float B = ex2f(tL);
                float D = ex2f(0.2f * tL);
                g_bd[h * NN + cb * 512 + np] = f16x2(B, D);     // lo=B, hi=D
            }
            atomicMax(&g_Tbits[h], emax);
        }
    }

    // ---- V^T f16 write, permuted: contiguous per block ----
    {
        __half* vbase = g_vh + (size_t)h * FO * NN + (size_t)cb * 512 + rb4 * 128 + r;
#pragma unroll
        for (int k = 0; k < 8; ++k)
#pragma unroll
            for (int i = 0; i < 4; ++i)
                vbase[(size_t)(c0 + k) * NN + 32 * i] = __float2half(v[i][k]);
    }

    // ---- adjacency pack, permuted via ballot ----
    {
        const int lane = t & 31;
        const int warp_g = (cb * gridDim.x + rb) * 8 + (t >> 5);   // 0..2047
#pragma unroll 2
        for (int task = warp_g; task < NN * 16; task += 2048) {
            const int i = task >> 4, jb = task & 15;
            const int4* p4 = (const int4*)(adj + (size_t)i * NN + jb * 256 + lane * 8);
            int4 a = p4[0], b = p4[1];
            unsigned byt =
                (unsigned)(a.x != 0)        | ((unsigned)(a.y != 0) << 1) |
                ((unsigned)(a.z != 0) << 2) | ((unsigned)(a.w != 0) << 3) |
                ((unsigned)(b.x != 0) << 4) | ((unsigned)(b.y != 0) << 5) |
                ((unsigned)(b.z != 0) << 6) | ((unsigned)(b.w != 0) << 7);
            unsigned wsel = 0;
#pragma unroll
            for (int c = 0; c < 8; ++c) {
                unsigned bal = __ballot_sync(0xFFFFFFFFu, (byt >> c) & 1u);
                if (lane == c) wsel = bal;
            }
            if (lane < 8)
                g_adjb[(size_t)i * (NN / 32) + lane * 16 + jb] = wsel;
        }
    }
}

// ---------------- kernel C: factorized masked-softmax @ V + fused combine ----------------
// w = max(A'_i*B_j, C'_i*D_j): exp factorizes over the rank-1 score; leaky-relu
// commutes with max through monotone exp2. No MUFU/cvt in the inner loop.
__global__ void __launch_bounds__(128, 4)
k_attn_mma(const unsigned* __restrict__ adjb, float* __restrict__ part,
           float* __restrict__ psums, float* __restrict__ outp) {
    extern __shared__ float dynf[];
    __half* svh = (__half*)dynf;
    __shared__ unsigned s_old;

    const int head  = blockIdx.x;
    const int ibase = blockIdx.y * 128;
    const int spl   = blockIdx.z;
    const int jbase = spl * JSPL;
    const int t     = threadIdx.x;
    const int wid   = t >> 5;
    const int lane  = t & 31;
    const int g     = lane >> 2;
    const int tg4   = lane & 3;

    const int rbase = ibase + wid * 32 + g;

    const float Th = decf(g_Tbits[head]);
    uint32_t A2[4], C2[4];                       // f16x2 dup row factors
#pragma unroll
    for (int rg = 0; rg < 4; ++rg) {
        float src = g_src[head * NN + rbase + rg * 8];
        float e0 = src + Th;
        float mm = fmaxf(e0, 0.2f * e0) * LOG2E; // >= scaled row max
        float sL = src * LOG2E;
        float Ap = ex2f(sL - mm);
        float Cp = ex2f(fmaf(0.2f, sL, -mm));
        A2[rg] = f16x2(Ap, Ap);
        C2[rg] = f16x2(Cp, Cp);
    }

    const unsigned* abase = adjb + (size_t)rbase * (NN / 32) + (jbase / 32);
    const __half* vhp = g_vh + (size_t)head * FO * NN + jbase;
    const unsigned* bdp = g_bd + (size_t)head * NN + jbase;

    const uint32_t svb = smem_u32(dynf);
    const uint32_t stb = svb + 3 * STG_V;
    const uint2* stp = (const uint2*)((const char*)dynf + 3 * STG_V);

    for (int idx = t; idx < 3 * 8 * VSTR; idx += 128) {
        int st = idx / (8 * VSTR), rem = idx % (8 * VSTR);
        int rr = rem / VSTR, kk = rem % VSTR;
        svh[st * (STG_V / 2) + (64 + rr) * VSTR + kk] =
            (rr == 0) ? __float2half(1.0f) : __float2half(0.0f);
    }

    float acc[2][9][4];
#pragma unroll
    for (int gr = 0; gr < 2; ++gr)
#pragma unroll
        for (int nb = 0; nb < 9; ++nb)
#pragma unroll
            for (int q = 0; q < 4; ++q) acc[gr][nb][q] = 0.f;

    auto load_tile = [&](int kt, int st) {
        const __half* base = vhp + (size_t)kt * KT;
        const uint32_t sb = svb + (uint32_t)st * STG_V;
#pragma unroll
        for (int u = 0; u < 4; ++u) {
            int idx = t + u * 128;
            int r = idx >> 3, q = idx & 7;
            cp16(sb + (uint32_t)r * (VSTR * 2) + (uint32_t)q * 16,
                 base + (size_t)r * NN + q * 8);
        }
        if (t < 16)
            cp16(stb + (uint32_t)st * STG_T + (uint32_t)t * 16, bdp + kt * 64 + t * 4);
        cp_commit();
    };
    auto load_adj = [&](int kt, unsigned long long wb[4]) {
#pragma unroll
        for (int rg = 0; rg < 4; ++rg) {
            uint2 w2 = *(const uint2*)(abase + (size_t)rg * 8 * (NN / 32) + 2 * kt);
            wb[rg] = (unsigned long long)w2.x | ((unsigned long long)w2.y << 32);
        }
    };

    load_tile(0, 0);
    load_tile(1, 1);
    unsigned long long wbcur[4], wbnext[4];
    load_adj(0, wbcur);

    for (int kt = 0; kt < NKT; ++kt) {
        const int st = kt % 3;
        if (kt + 2 < NKT) {
            asm volatile("cp.async.wait_group 1;" ::: "memory");
        } else {
            asm volatile("cp.async.wait_group 0;" ::: "memory");
        }
        __syncthreads();
        if (kt + 2 < NKT) load_tile(kt + 2, (kt + 2) % 3);
        if (kt + 1 < NKT) load_adj(kt + 1, wbnext);

        const __half* sVs = svh + st * (STG_V / 2);
        const uint2* stq = stp + st * (STG_T / 8);

#pragma unroll
        for (int ks = 0; ks < 4; ++ks) {
            const uint2 u1 = stq[ks * 8 + tg4];       // {B,D} for j, j+1
            const uint2 u2 = stq[ks * 8 + 4 + tg4];   // {B,D} for j+8, j+9
            const uint32_t B2a = prmt(u1.x, u1.y, 0x5410u);
            const uint32_t D2a = prmt(u1.x, u1.y, 0x7632u);
            const uint32_t B2b = prmt(u2.x, u2.y, 0x5410u);
            const uint32_t D2b = prmt(u2.x, u2.y, 0x7632u);
            const int shft = ks * 16 + 2 * tg4;

            uint32_t alo[4], ahi[4];
#pragma unroll
            for (int rg = 0; rg < 4; ++rg) {
                const unsigned bs = (unsigned)(wbcur[rg] >> shft);
                uint32_t wA = hmax2(hmul2(A2[rg], B2a), hmul2(C2[rg], D2a));
                unsigned mA = ((bs & 1u) * 0xFFFFu) | ((bs & 2u) * 0x7FFF8000u);
                alo[rg] = wA & mA;
                uint32_t wB = hmax2(hmul2(A2[rg], B2b), hmul2(C2[rg], D2b));
                const unsigned bs8 = bs >> 8;
                unsigned mB = ((bs8 & 1u) * 0xFFFFu) | ((bs8 & 2u) * 0x7FFF8000u);
                ahi[rg] = wB & mB;
            }
            const int kb = ks * 16 + 2 * tg4;
#pragma unroll
            for (int nb = 0; nb < 9; ++nb) {
                const __half* brow = sVs + (nb * 8 + g) * VSTR + kb;
                uint32_t b0 = *(const uint32_t*)(brow);
                uint32_t b1 = *(const uint32_t*)(brow + 8);
                mma_f16(acc[0][nb], alo[0], alo[1], ahi[0], ahi[1], b0, b1);
                mma_f16(acc[1][nb], alo[2], alo[3], ahi[2], ahi[3], b0, b1);
            }
        }
#pragma unroll
        for (int rg = 0; rg < 4; ++rg) wbcur[rg] = wbnext[rg];
    }

    // ---- denominator partials ----
    float* psp = psums + (size_t)spl * (NH * NN) + head * NN;
    if (tg4 == 0) {
        psp[rbase]      = acc[0][8][0];
        psp[rbase + 8]  = acc[0][8][2];
        psp[rbase + 16] = acc[1][8][0];
        psp[rbase + 24] = acc[1][8][2];
    }

    // ---- numerator partials ----
    float* pp = part + (size_t)spl * (NH * NN * FO) + ((size_t)head * NN) * FO;
#pragma unroll
    for (int gr = 0; gr < 2; ++gr) {
        float* o1 = pp + (size_t)(rbase + gr * 16) * FO + 2 * tg4;
        float* o2 = o1 + 8 * FO;
#pragma unroll
        for (int nb = 0; nb < 8; ++nb) {
            *(float2*)(o1 + nb * 8) = make_float2(acc[gr][nb][0], acc[gr][nb][1]);
            *(float2*)(o2 + nb * 8) = make_float2(acc[gr][nb][2], acc[gr][nb][3]);
        }
    }

    // ---- fused combine: last split-block for this (head, i-tile) ----
    __threadfence();
    __syncthreads();
    if (t == 0) s_old = atomicAdd(&g_flag[head * (NN / 128) + blockIdx.y], 1u);
    __syncthreads();
    if (s_old == NSPL - 1) {
        __threadfence();
        const size_t rowoff = ((size_t)head * NN + ibase) * FO;
        const float4* n0 = (const float4*)(part + rowoff);
        const float4* n1 = (const float4*)(part + (size_t)NH * NN * FO + rowoff);
        const float* s0 = psums + head * NN + ibase;
        const float* s1 = psums + NH * NN + head * NN + ibase;
        float4* op = (float4*)(outp + rowoff);
        for (int idx = t; idx < 128 * FO / 4; idx += 128) {
            int row = idx >> 4;
            float s = s0[row] + s1[row];
            float inv = (s > 0.f) ? 1.0f / s : 0.f;
            float4 a = n0[idx], b = n1[idx];
            float4 o;
            o.x = (a.x + b.x) * inv;
            o.y = (a.y + b.y) * inv;
            o.z = (a.z + b.z) * inv;
            o.w = (a.w + b.w) * inv;
            op[idx] = o;
        }
    }
}

// ---------------- host launcher ----------------
extern "C" void kernel_launch(void* const* d_in, const int* in_sizes, int n_in,
                              void* d_out, int out_size) {
    const float* H = nullptr; const int* adj = nullptr;
    const float* W = nullptr; const float* a = nullptr;
    for (int i = 0; i < n_in; ++i) {
        switch (in_sizes[i]) {
            case NN * FIN:    H   = (const float*)d_in[i]; break;
            case NN * NN:     adj = (const int*)d_in[i];   break;
            case FIN * FTOT:  W   = (const float*)d_in[i]; break;
            case NH * 2 * FO: a   = (const float*)d_in[i]; break;
        }
    }
    float* out = (float*)d_out;

    unsigned* adjb; cudaGetSymbolAddress((void**)&adjb, g_adjb);
    float* part;    cudaGetSymbolAddress((void**)&part, g_part);
    float* psums;   cudaGetSymbolAddress((void**)&psums, g_psum);

    cudaFuncSetAttribute(k_attn_mma, cudaFuncAttributeMaxDynamicSharedMemorySize,
                         SMEM_DYN);

    k_gemmpack<<<dim3(NN / 128, NH), 256>>>(H, W, a, adj);
    k_attn_mma<<<dim3(NH, NN / 128, NSPL), 128, SMEM_DYN>>>(adjb, part, psums, out);
}